// round 4
// baseline (speedup 1.0000x reference)
#include <cuda_runtime.h>
#include <math.h>

#define Nn 8192
#define IN_F 256
#define OUT_F 128
#define NWORDS 256   // bitmap words per row (8192 bits)
#define CAP 2048     // fast-path neighbor list capacity (expected degree ~32)
#define SS_BLOCKS 64
#define SS_ROWS (Nn / SS_BLOCKS)   // 128 rows per sscore block

// ---------------- device scratch (no allocs allowed) ----------------
__device__ float    g_hc[Nn * OUT_F];          // 4 MB
__device__ unsigned g_adj[Nn * NWORDS];        // 8 MB adjacency bitmap
__device__ float    g_sc_src[Nn];
__device__ float    g_ss_src[Nn];
__device__ float2   g_sd[Nn];                  // (sc_dst, ss_dst) packed
__device__ int      g_isi32 = 0;               // reset at end of k_attn

__device__ __forceinline__ float lrelu(float x) { return x > 0.f ? x : 0.01f * x; }

// ---------------- reductions (start and end with __syncthreads) ----------------
__device__ float blockReduceMax(float v, float* red) {
    __syncthreads();
    #pragma unroll
    for (int o = 16; o; o >>= 1) v = fmaxf(v, __shfl_xor_sync(0xffffffffu, v, o));
    int w = threadIdx.x >> 5;
    if ((threadIdx.x & 31) == 0) red[w] = v;
    __syncthreads();
    if (threadIdx.x < 32) {
        float x = (threadIdx.x < (blockDim.x >> 5)) ? red[threadIdx.x] : -INFINITY;
        #pragma unroll
        for (int o = 4; o; o >>= 1) x = fmaxf(x, __shfl_xor_sync(0xffffffffu, x, o));
        if (threadIdx.x == 0) red[0] = x;
    }
    __syncthreads();
    return red[0];
}

__device__ float blockReduceSum(float v, float* red) {
    __syncthreads();
    #pragma unroll
    for (int o = 16; o; o >>= 1) v += __shfl_xor_sync(0xffffffffu, v, o);
    int w = threadIdx.x >> 5;
    if ((threadIdx.x & 31) == 0) red[w] = v;
    __syncthreads();
    if (threadIdx.x < 32) {
        float x = (threadIdx.x < (blockDim.x >> 5)) ? red[threadIdx.x] : 0.f;
        #pragma unroll
        for (int o = 4; o; o >>= 1) x += __shfl_xor_sync(0xffffffffu, x, o);
        if (threadIdx.x == 0) red[0] = x;
    }
    __syncthreads();
    return red[0];
}

// ---------------- kernels ----------------
// Fused: vectorized bitmap clear + int32/int64 format detection.
// g_isi32 is only atomicOr'd here (reset happens at the tail of k_attn),
// so there is no reset/set race within this kernel.
__global__ void k_init(const int* __restrict__ p32, int E) {
    int i = blockIdx.x * blockDim.x + threadIdx.x;
    ((uint4*)g_adj)[i] = make_uint4(0u, 0u, 0u, 0u);
    if (i < E) {
        if (p32[2 * i + 1] != 0) atomicOr(&g_isi32, 1);
    }
}

__global__ void k_edges(const int* __restrict__ p32, int E) {
    int e = blockIdx.x * blockDim.x + threadIdx.x;
    if (e >= E) return;
    int r, c;
    if (g_isi32) {
        r = p32[e];
        c = p32[E + e];
    } else {
        const long long* p64 = (const long long*)p32;
        r = (int)p64[e];
        c = (int)p64[E + e];
    }
    if ((unsigned)r < Nn && (unsigned)c < Nn)
        atomicOr(&g_adj[r * NWORDS + (c >> 5)], 1u << (c & 31));
}

// Structure scores, with the hs-GEMM fold (vs1/vs2/bias) computed per block.
// Each block: phase 1 computes vs = Ws_w^T @ as_half (redundantly, L2-resident),
// phase 2 handles SS_ROWS rows of the feature softmax + dot.
__global__ void __launch_bounds__(256) k_sscore(const float* __restrict__ hstruct,
                                                const float* __restrict__ Ws_w,
                                                const float* __restrict__ Ws_b,
                                                const float* __restrict__ as_w) {
    __shared__ float svs1[IN_F], svs2[IN_F];
    __shared__ float sbias[2];
    int tid = threadIdx.x;
    int warp = tid >> 5, lane = tid & 31;

    // phase 1: vs1[k], vs2[k] for k = tid (256 threads cover IN_F)
    {
        float v1 = 0.f, v2 = 0.f;
        #pragma unroll 16
        for (int f = 0; f < OUT_F; f++) {
            float w = Ws_w[f * IN_F + tid];
            v1 += w * as_w[f];
            v2 += w * as_w[OUT_F + f];
        }
        svs1[tid] = v1;
        svs2[tid] = v2;
        if (tid < 32) {
            float b1 = 0.f, b2 = 0.f;
            #pragma unroll
            for (int i = 0; i < 4; i++) {
                int f = tid + 32 * i;
                float wb = Ws_b[f];
                b1 += wb * as_w[f];
                b2 += wb * as_w[OUT_F + f];
            }
            #pragma unroll
            for (int o = 16; o; o >>= 1) {
                b1 += __shfl_xor_sync(0xffffffffu, b1, o);
                b2 += __shfl_xor_sync(0xffffffffu, b2, o);
            }
            if (tid == 0) { sbias[0] = b1; sbias[1] = b2; }
        }
    }
    __syncthreads();
    float bs1 = sbias[0], bs2 = sbias[1];

    // phase 2: rows (8 warps, warp handles SS_ROWS/8 rows)
    for (int r = 0; r < SS_ROWS / 8; r++) {
        int row = blockIdx.x * SS_ROWS + r * 8 + warp;
        const float* x = hstruct + (size_t)row * IN_F;
        float v[8];
        float m = -INFINITY;
        #pragma unroll
        for (int e = 0; e < 8; e++) { v[e] = x[lane + 32 * e]; m = fmaxf(m, v[e]); }
        #pragma unroll
        for (int o = 16; o; o >>= 1) m = fmaxf(m, __shfl_xor_sync(0xffffffffu, m, o));
        float z = 0.f, d1 = 0.f, d2 = 0.f;
        #pragma unroll
        for (int e = 0; e < 8; e++) {
            float ex = __expf(v[e] - m);
            z  += ex;
            d1 += ex * svs1[lane + 32 * e];
            d2 += ex * svs2[lane + 32 * e];
        }
        #pragma unroll
        for (int o = 16; o; o >>= 1) {
            z  += __shfl_xor_sync(0xffffffffu, z,  o);
            d1 += __shfl_xor_sync(0xffffffffu, d1, o);
            d2 += __shfl_xor_sync(0xffffffffu, d2, o);
        }
        if (lane == 0) {
            g_ss_src[row]  = d1 / z + bs1;
            g_sd[row].y    = d2 / z + bs2;
        }
    }
}

// hc = h_context @ Wc_w^T + Wc_b  (M=8192, N=128, K=256) fp32 tiled SGEMM,
// with fused context-score epilogue.
#define BM 64
#define BN 128
#define BK 32
__global__ void __launch_bounds__(256) k_gemm(const float* __restrict__ A,
                                              const float* __restrict__ W,
                                              const float* __restrict__ b,
                                              const float* __restrict__ ac_w) {
    __shared__ float As[BK][BM + 4];
    __shared__ float Ws[BK][BN + 4];
    int tid = threadIdx.x;
    int lane = tid & 31;
    int block_m = blockIdx.x * BM;
    int tn = lane * 4;         // 0..124
    int tm = (tid >> 5) * 8;   // 0..56
    float acc[8][4] = {};
    for (int k0 = 0; k0 < IN_F; k0 += BK) {
        #pragma unroll
        for (int i = 0; i < 2; i++) {
            int l = tid + i * 256;            // 0..511
            int row = l >> 3;
            int col4 = (l & 7) * 4;
            float4 v = *(const float4*)&A[(size_t)(block_m + row) * IN_F + k0 + col4];
            As[col4 + 0][row] = v.x; As[col4 + 1][row] = v.y;
            As[col4 + 2][row] = v.z; As[col4 + 3][row] = v.w;
        }
        #pragma unroll
        for (int i = 0; i < 4; i++) {
            int l = tid + i * 256;            // 0..1023
            int row = l >> 3;
            int col4 = (l & 7) * 4;
            float4 v = *(const float4*)&W[(size_t)row * IN_F + k0 + col4];
            Ws[col4 + 0][row] = v.x; Ws[col4 + 1][row] = v.y;
            Ws[col4 + 2][row] = v.z; Ws[col4 + 3][row] = v.w;
        }
        __syncthreads();
        #pragma unroll
        for (int k = 0; k < BK; k++) {
            float4 a0 = *(const float4*)&As[k][tm];
            float4 a1 = *(const float4*)&As[k][tm + 4];
            float4 w0 = *(const float4*)&Ws[k][tn];
            float af[8] = {a0.x, a0.y, a0.z, a0.w, a1.x, a1.y, a1.z, a1.w};
            float wf[4] = {w0.x, w0.y, w0.z, w0.w};
            #pragma unroll
            for (int i = 0; i < 8; i++)
                #pragma unroll
                for (int j = 0; j < 4; j++)
                    acc[i][j] += af[i] * wf[j];
        }
        __syncthreads();
    }
    float bb[4], ac1[4], ac2[4];
    #pragma unroll
    for (int j = 0; j < 4; j++) {
        bb[j]  = b[tn + j];
        ac1[j] = ac_w[tn + j];
        ac2[j] = ac_w[OUT_F + tn + j];
    }
    #pragma unroll
    for (int i = 0; i < 8; i++) {
        int row = block_m + tm + i;
        float s1 = 0.f, s2 = 0.f;
        float4 hv;
        float* hp = (float*)&hv;
        #pragma unroll
        for (int j = 0; j < 4; j++) {
            float h = acc[i][j] + bb[j];
            hp[j] = h;
            s1 += h * ac1[j];
            s2 += h * ac2[j];
        }
        *(float4*)&g_hc[(size_t)row * OUT_F + tn] = hv;
        // warp covers all 128 columns for this row -> full reduction
        #pragma unroll
        for (int o = 16; o; o >>= 1) {
            s1 += __shfl_xor_sync(0xffffffffu, s1, o);
            s2 += __shfl_xor_sync(0xffffffffu, s2, o);
        }
        if (lane == 0) { g_sc_src[row] = s1; g_sd[row].x = s2; }
    }
}

// Per-row sparse masked softmax + weighted hc gather.
// Single gather pass: pass 1 stores alpha while computing the max.
__global__ void __launch_bounds__(256) k_attn(float* __restrict__ out,
                                              const float* __restrict__ Ws_coff,
                                              const float* __restrict__ Wc_coff) {
    __shared__ float wl[CAP];
    __shared__ unsigned short jl[CAP];
    __shared__ float red[32];
    __shared__ int s_cnt;
    __shared__ float part2[OUT_F];

    int row = blockIdx.x;
    int tid = threadIdx.x;  // 256 threads, one bitmap word each
    float ca = fabsf(Ws_coff[0]);   // multiplies alpha_c (per reference)
    float cs = fabsf(Wc_coff[0]);   // multiplies alpha_s
    float sci = g_sc_src[row], ssi = g_ss_src[row];
    unsigned word = g_adj[row * NWORDS + tid];
    int f = tid & (OUT_F - 1);
    int part = tid >> 7;  // 0 or 1

    if (tid == 0) s_cnt = 0;
    if (row == 0 && tid == 1) g_isi32 = 0;   // reset detect flag for next replay
    __syncthreads();

    // pass 1: alpha per set bit -> smem list (guarded), track max
    int o = atomicAdd(&s_cnt, __popc(word));
    float m = -INFINITY;
    unsigned w = word;
    while (w) {
        int bpos = __ffs(w) - 1; w &= w - 1;
        int j = (tid << 5) + bpos;
        float2 sd = g_sd[j];
        float a = ca * lrelu(sci + sd.x) + cs * lrelu(ssi + sd.y);
        m = fmaxf(m, a);
        if (o < CAP) { wl[o] = a; jl[o] = (unsigned short)j; }
        o++;
    }
    m = blockReduceMax(m, red);   // syncs also finalize s_cnt and wl/jl
    int total = s_cnt;

    if (total == 0) {
        // masked row == all -9e15 -> uniform softmax -> mean of hc
        if (part == 0) {
            float acc = 0.f;
            for (int j = 0; j < Nn; j++) acc += g_hc[(size_t)j * OUT_F + f];
            out[(size_t)row * OUT_F + f] = acc / (float)Nn;
        }
        return;
    }

    if (total <= CAP) {
        // exp sweep over compacted smem list (no second gather)
        float zloc = 0.f;
        for (int k = tid; k < total; k += 256) {
            float e = __expf(wl[k] - m);
            wl[k] = e;
            zloc += e;
        }
        float Z = blockReduceSum(zloc, red);
        float inv = 1.f / Z;
        float acc = 0.f;
        for (int k = part; k < total; k += 2)
            acc += wl[k] * g_hc[(size_t)jl[k] * OUT_F + f];
        if (part == 1) part2[f] = acc;
        __syncthreads();
        if (part == 0)
            out[(size_t)row * OUT_F + f] = (acc + part2[f]) * inv;
        return;
    }

    // slow path (degree > CAP): recompute Z, then chunked compaction+gather
    {
        float zloc = 0.f;
        w = word;
        while (w) {
            int bpos = __ffs(w) - 1; w &= w - 1;
            int j = (tid << 5) + bpos;
            float2 sd = g_sd[j];
            float a = ca * lrelu(sci + sd.x) + cs * lrelu(ssi + sd.y);
            zloc += __expf(a - m);
        }
        float Z = blockReduceSum(zloc, red);
        float inv = 1.f / Z;
        float acc = 0.f;
        for (int c = 0; c < NWORDS / 32; c++) {   // 32 words = 1024 bits per chunk
            __syncthreads();
            if (tid == 0) s_cnt = 0;
            __syncthreads();
            if (tid < 32) {
                unsigned wd = g_adj[row * NWORDS + c * 32 + tid];
                int oo = atomicAdd(&s_cnt, __popc(wd));
                while (wd) {
                    int bpos = __ffs(wd) - 1; wd &= wd - 1;
                    int j = ((c * 32 + tid) << 5) + bpos;
                    float2 sd = g_sd[j];
                    float a = ca * lrelu(sci + sd.x) + cs * lrelu(ssi + sd.y);
                    wl[oo] = __expf(a - m);
                    jl[oo] = (unsigned short)j;
                    oo++;
                }
            }
            __syncthreads();
            int cc = s_cnt;
            for (int k = part; k < cc; k += 2)
                acc += wl[k] * g_hc[(size_t)jl[k] * OUT_F + f];
        }
        if (part == 1) part2[f] = acc;
        __syncthreads();
        if (part == 0)
            out[(size_t)row * OUT_F + f] = (acc + part2[f]) * inv;
    }
}

// ---------------- launch ----------------
extern "C" void kernel_launch(void* const* d_in, const int* in_sizes, int n_in,
                              void* d_out, int out_size) {
    const float* h_context   = (const float*)d_in[0];
    const float* h_structure = (const float*)d_in[1];
    const int*   edge        = (const int*)d_in[2];   // int32 or int64, detected on device
    const float* Wc_w        = (const float*)d_in[3];
    const float* Wc_b        = (const float*)d_in[4];
    const float* Ws_w        = (const float*)d_in[5];
    const float* Ws_b        = (const float*)d_in[6];
    const float* ac_w        = (const float*)d_in[7];
    const float* as_w        = (const float*)d_in[8];
    const float* Ws_coff     = (const float*)d_in[9];
    const float* Wc_coff     = (const float*)d_in[10];
    float* out = (float*)d_out;
    int E = in_sizes[2] / 2;

    k_init<<<(Nn * NWORDS / 4) / 256, 256>>>(edge, E);
    k_edges<<<(E + 255) / 256, 256>>>(edge, E);
    k_sscore<<<SS_BLOCKS, 256>>>(h_structure, Ws_w, Ws_b, as_w);
    k_gemm<<<Nn / BM, 256>>>(h_context, Wc_w, Wc_b, ac_w);
    k_attn<<<Nn, 256>>>(out, Ws_coff, Wc_coff);
}

// round 5
// speedup vs baseline: 1.1669x; 1.1669x over previous
#include <cuda_runtime.h>
#include <math.h>

#define Nn 8192
#define IN_F 256
#define OUT_F 128
#define NWORDS 256   // bitmap words per row (8192 bits)
#define CAP 2048     // fast-path neighbor list capacity (expected degree ~32)

// ---------------- device scratch (no allocs allowed) ----------------
__device__ float    g_hc[Nn * OUT_F];          // 4 MB
__device__ unsigned g_adj[Nn * NWORDS];        // 8 MB adjacency bitmap
__device__ float    g_sc_src[Nn];
__device__ float    g_ss_src[Nn];
__device__ float2   g_sd[Nn];                  // (sc_dst, ss_dst) packed
__device__ float    g_vs1[IN_F], g_vs2[IN_F];  // hs-GEMM fold vectors
__device__ float    g_scal[4];                 // ca, cs, bs1, bs2
__device__ int      g_isi32 = 0;               // reset at end of k_attn

__device__ __forceinline__ float lrelu(float x) { return x > 0.f ? x : 0.01f * x; }

// ---------------- reductions (start and end with __syncthreads) ----------------
__device__ float blockReduceMax(float v, float* red) {
    __syncthreads();
    #pragma unroll
    for (int o = 16; o; o >>= 1) v = fmaxf(v, __shfl_xor_sync(0xffffffffu, v, o));
    int w = threadIdx.x >> 5;
    if ((threadIdx.x & 31) == 0) red[w] = v;
    __syncthreads();
    if (threadIdx.x < 32) {
        float x = (threadIdx.x < (blockDim.x >> 5)) ? red[threadIdx.x] : -INFINITY;
        #pragma unroll
        for (int o = 4; o; o >>= 1) x = fmaxf(x, __shfl_xor_sync(0xffffffffu, x, o));
        if (threadIdx.x == 0) red[0] = x;
    }
    __syncthreads();
    return red[0];
}

__device__ float blockReduceSum(float v, float* red) {
    __syncthreads();
    #pragma unroll
    for (int o = 16; o; o >>= 1) v += __shfl_xor_sync(0xffffffffu, v, o);
    int w = threadIdx.x >> 5;
    if ((threadIdx.x & 31) == 0) red[w] = v;
    __syncthreads();
    if (threadIdx.x < 32) {
        float x = (threadIdx.x < (blockDim.x >> 5)) ? red[threadIdx.x] : 0.f;
        #pragma unroll
        for (int o = 4; o; o >>= 1) x += __shfl_xor_sync(0xffffffffu, x, o);
        if (threadIdx.x == 0) red[0] = x;
    }
    __syncthreads();
    return red[0];
}

// ---------------- kernels ----------------
// Fused: vectorized bitmap clear + int32/int64 detection + g_vs zero (block 0).
__global__ void k_init(const int* __restrict__ p32, int E) {
    int i = blockIdx.x * blockDim.x + threadIdx.x;
    ((uint4*)g_adj)[i] = make_uint4(0u, 0u, 0u, 0u);
    if (blockIdx.x == 0) {
        g_vs1[threadIdx.x] = 0.f;
        g_vs2[threadIdx.x] = 0.f;
    }
    if (i < E) {
        if (p32[2 * i + 1] != 0) atomicOr(&g_isi32, 1);
    }
}

// Edge bitmap build; blocks 0..7 additionally accumulate the hs-GEMM fold
// (vs = Ws_w^T @ as_half) via coalesced partials + atomicAdd; block 8 does
// bias dots + coefficient abs.
__global__ void k_edges(const int* __restrict__ p32, int E,
                        const float* __restrict__ Ws_w,
                        const float* __restrict__ Ws_b,
                        const float* __restrict__ as_w,
                        const float* __restrict__ Ws_coff,
                        const float* __restrict__ Wc_coff) {
    int tid = threadIdx.x;
    int e = blockIdx.x * blockDim.x + tid;
    if (e < E) {
        int r, c;
        if (g_isi32) {
            r = p32[e];
            c = p32[E + e];
        } else {
            const long long* p64 = (const long long*)p32;
            r = (int)p64[e];
            c = (int)p64[E + e];
        }
        if ((unsigned)r < Nn && (unsigned)c < Nn)
            atomicOr(&g_adj[r * NWORDS + (c >> 5)], 1u << (c & 31));
    }
    if (blockIdx.x < 8) {
        // fold partial: f-range [blk*16, blk*16+16), k = tid (coalesced rows)
        float v1 = 0.f, v2 = 0.f;
        #pragma unroll
        for (int i = 0; i < 16; i++) {
            int f = blockIdx.x * 16 + i;
            float w = Ws_w[f * IN_F + tid];
            v1 += w * as_w[f];
            v2 += w * as_w[OUT_F + f];
        }
        atomicAdd(&g_vs1[tid], v1);
        atomicAdd(&g_vs2[tid], v2);
    } else if (blockIdx.x == 8 && tid < 32) {
        float b1 = 0.f, b2 = 0.f;
        #pragma unroll
        for (int i = 0; i < 4; i++) {
            int f = tid + 32 * i;
            float wb = Ws_b[f];
            b1 += wb * as_w[f];
            b2 += wb * as_w[OUT_F + f];
        }
        #pragma unroll
        for (int o = 16; o; o >>= 1) {
            b1 += __shfl_xor_sync(0xffffffffu, b1, o);
            b2 += __shfl_xor_sync(0xffffffffu, b2, o);
        }
        if (tid == 0) {
            g_scal[0] = fabsf(Ws_coff[0]);  // multiplies alpha_c
            g_scal[1] = fabsf(Wc_coff[0]);  // multiplies alpha_s
            g_scal[2] = b1;
            g_scal[3] = b2;
        }
    }
}

// Structure scores: warp per row, softmax over 256 features dotted with g_vs.
__global__ void k_sscore(const float* __restrict__ hstruct) {
    int warp = (blockIdx.x * blockDim.x + threadIdx.x) >> 5;
    int lane = threadIdx.x & 31;
    if (warp >= Nn) return;
    const float* x = hstruct + (size_t)warp * IN_F;
    float v[8], w1[8], w2[8];
    float m = -INFINITY;
    #pragma unroll
    for (int e = 0; e < 8; e++) {
        v[e]  = x[lane + 32 * e];
        w1[e] = g_vs1[lane + 32 * e];
        w2[e] = g_vs2[lane + 32 * e];
        m = fmaxf(m, v[e]);
    }
    #pragma unroll
    for (int o = 16; o; o >>= 1) m = fmaxf(m, __shfl_xor_sync(0xffffffffu, m, o));
    float z = 0.f, d1 = 0.f, d2 = 0.f;
    #pragma unroll
    for (int e = 0; e < 8; e++) {
        float ex = __expf(v[e] - m);
        z  += ex;
        d1 += ex * w1[e];
        d2 += ex * w2[e];
    }
    #pragma unroll
    for (int o = 16; o; o >>= 1) {
        z  += __shfl_xor_sync(0xffffffffu, z,  o);
        d1 += __shfl_xor_sync(0xffffffffu, d1, o);
        d2 += __shfl_xor_sync(0xffffffffu, d2, o);
    }
    if (lane == 0) {
        g_ss_src[warp] = d1 / z + g_scal[2];
        g_sd[warp].y   = d2 / z + g_scal[3];
    }
}

// hc = h_context @ Wc_w^T + Wc_b  (M=8192, N=128, K=256) fp32 SGEMM,
// double-buffered smem + register prefetch, fused context-score epilogue.
#define BM 64
#define BN 128
#define BK 32
#define KTILES (IN_F / BK)
__global__ void __launch_bounds__(256) k_gemm(const float* __restrict__ A,
                                              const float* __restrict__ W,
                                              const float* __restrict__ b,
                                              const float* __restrict__ ac_w) {
    __shared__ float As[2][BK][BM + 4];
    __shared__ float Ws[2][BK][BN + 4];
    int tid = threadIdx.x;
    int lane = tid & 31;
    int block_m = blockIdx.x * BM;
    int tn = lane * 4;         // 0..124
    int tm = (tid >> 5) * 8;   // 0..56

    // per-thread LDG slices (fixed across tiles except k0)
    int arow0 = tid >> 3;              // 0..31  (i=0)
    int acol  = (tid & 7) * 4;
    const float* Aptr0 = &A[(size_t)(block_m + arow0) * IN_F + acol];
    const float* Aptr1 = Aptr0 + (size_t)32 * IN_F;   // i=1 -> rows 32..63
    int wrow0 = tid >> 1;              // 0..127 stepping 64 per i? no:
    // W: l = tid + i*256, row = l>>1? careful: 128 rows, 8 col-groups -> l>>3 gives 0..127 over i=0..3
    // keep original mapping: row = (tid + i*256) >> 3, col4 = ((tid+i*256)&7)*4 ; (tid+i*256)&7 == tid&7
    const float* Wptr = &W[(size_t)(tid >> 3) * IN_F + acol];

    float4 ra0, ra1, rw0, rw1, rw2, rw3;
    #define LDG_TILE(k0)                                                    \
        ra0 = *(const float4*)(Aptr0 + (k0));                               \
        ra1 = *(const float4*)(Aptr1 + (k0));                               \
        rw0 = *(const float4*)(Wptr + (k0));                                \
        rw1 = *(const float4*)(Wptr + (size_t)32 * IN_F + (k0));            \
        rw2 = *(const float4*)(Wptr + (size_t)64 * IN_F + (k0));            \
        rw3 = *(const float4*)(Wptr + (size_t)96 * IN_F + (k0));

    #define STS_TILE(buf)                                                   \
        {                                                                   \
            int r0 = tid >> 3, c0 = (tid & 7) * 4;                          \
            As[buf][c0 + 0][r0] = ra0.x; As[buf][c0 + 1][r0] = ra0.y;       \
            As[buf][c0 + 2][r0] = ra0.z; As[buf][c0 + 3][r0] = ra0.w;       \
            As[buf][c0 + 0][r0 + 32] = ra1.x; As[buf][c0 + 1][r0 + 32] = ra1.y; \
            As[buf][c0 + 2][r0 + 32] = ra1.z; As[buf][c0 + 3][r0 + 32] = ra1.w; \
            Ws[buf][c0 + 0][r0] = rw0.x; Ws[buf][c0 + 1][r0] = rw0.y;       \
            Ws[buf][c0 + 2][r0] = rw0.z; Ws[buf][c0 + 3][r0] = rw0.w;       \
            Ws[buf][c0 + 0][r0 + 32] = rw1.x; Ws[buf][c0 + 1][r0 + 32] = rw1.y; \
            Ws[buf][c0 + 2][r0 + 32] = rw1.z; Ws[buf][c0 + 3][r0 + 32] = rw1.w; \
            Ws[buf][c0 + 0][r0 + 64] = rw2.x; Ws[buf][c0 + 1][r0 + 64] = rw2.y; \
            Ws[buf][c0 + 2][r0 + 64] = rw2.z; Ws[buf][c0 + 3][r0 + 64] = rw2.w; \
            Ws[buf][c0 + 0][r0 + 96] = rw3.x; Ws[buf][c0 + 1][r0 + 96] = rw3.y; \
            Ws[buf][c0 + 2][r0 + 96] = rw3.z; Ws[buf][c0 + 3][r0 + 96] = rw3.w; \
        }

    float acc[8][4] = {};
    LDG_TILE(0);
    STS_TILE(0);
    __syncthreads();

    #pragma unroll 1
    for (int kt = 0; kt < KTILES; kt++) {
        int cur = kt & 1;
        if (kt < KTILES - 1) { LDG_TILE((kt + 1) * BK); }
        #pragma unroll
        for (int k = 0; k < BK; k++) {
            float4 a0 = *(const float4*)&As[cur][k][tm];
            float4 a1 = *(const float4*)&As[cur][k][tm + 4];
            float4 w0 = *(const float4*)&Ws[cur][k][tn];
            float af[8] = {a0.x, a0.y, a0.z, a0.w, a1.x, a1.y, a1.z, a1.w};
            float wf[4] = {w0.x, w0.y, w0.z, w0.w};
            #pragma unroll
            for (int i = 0; i < 8; i++)
                #pragma unroll
                for (int j = 0; j < 4; j++)
                    acc[i][j] += af[i] * wf[j];
        }
        if (kt < KTILES - 1) {
            STS_TILE(cur ^ 1);
            __syncthreads();
        }
    }

    float bb[4], ac1[4], ac2[4];
    #pragma unroll
    for (int j = 0; j < 4; j++) {
        bb[j]  = b[tn + j];
        ac1[j] = ac_w[tn + j];
        ac2[j] = ac_w[OUT_F + tn + j];
    }
    #pragma unroll
    for (int i = 0; i < 8; i++) {
        int row = block_m + tm + i;
        float s1 = 0.f, s2 = 0.f;
        float4 hv;
        float* hp = (float*)&hv;
        #pragma unroll
        for (int j = 0; j < 4; j++) {
            float h = acc[i][j] + bb[j];
            hp[j] = h;
            s1 += h * ac1[j];
            s2 += h * ac2[j];
        }
        *(float4*)&g_hc[(size_t)row * OUT_F + tn] = hv;
        #pragma unroll
        for (int o = 16; o; o >>= 1) {
            s1 += __shfl_xor_sync(0xffffffffu, s1, o);
            s2 += __shfl_xor_sync(0xffffffffu, s2, o);
        }
        if (lane == 0) { g_sc_src[row] = s1; g_sd[row].x = s2; }
    }
}

// Per-row sparse masked softmax + weighted hc gather (single gather pass).
__global__ void __launch_bounds__(256) k_attn(float* __restrict__ out,
                                              const float* __restrict__ Ws_coff,
                                              const float* __restrict__ Wc_coff) {
    __shared__ float wl[CAP];
    __shared__ unsigned short jl[CAP];
    __shared__ float red[32];
    __shared__ int s_cnt;
    __shared__ float part2[OUT_F];

    int row = blockIdx.x;
    int tid = threadIdx.x;  // 256 threads, one bitmap word each
    float ca = fabsf(Ws_coff[0]);   // multiplies alpha_c (per reference)
    float cs = fabsf(Wc_coff[0]);   // multiplies alpha_s
    float sci = g_sc_src[row], ssi = g_ss_src[row];
    unsigned word = g_adj[row * NWORDS + tid];
    int f = tid & (OUT_F - 1);
    int part = tid >> 7;  // 0 or 1

    if (tid == 0) s_cnt = 0;
    if (row == 0 && tid == 1) g_isi32 = 0;   // reset detect flag for next replay
    __syncthreads();

    // pass 1: alpha per set bit -> smem list (guarded), track max
    int o = atomicAdd(&s_cnt, __popc(word));
    float m = -INFINITY;
    unsigned w = word;
    while (w) {
        int bpos = __ffs(w) - 1; w &= w - 1;
        int j = (tid << 5) + bpos;
        float2 sd = g_sd[j];
        float a = ca * lrelu(sci + sd.x) + cs * lrelu(ssi + sd.y);
        m = fmaxf(m, a);
        if (o < CAP) { wl[o] = a; jl[o] = (unsigned short)j; }
        o++;
    }
    m = blockReduceMax(m, red);   // syncs also finalize s_cnt and wl/jl
    int total = s_cnt;

    if (total == 0) {
        // masked row == all -9e15 -> uniform softmax -> mean of hc
        if (part == 0) {
            float acc = 0.f;
            for (int j = 0; j < Nn; j++) acc += g_hc[(size_t)j * OUT_F + f];
            out[(size_t)row * OUT_F + f] = acc / (float)Nn;
        }
        return;
    }

    if (total <= CAP) {
        float zloc = 0.f;
        for (int k = tid; k < total; k += 256) {
            float e = __expf(wl[k] - m);
            wl[k] = e;
            zloc += e;
        }
        float Z = blockReduceSum(zloc, red);
        float inv = 1.f / Z;
        float acc = 0.f;
        #pragma unroll 4
        for (int k = part; k < total; k += 2)
            acc += wl[k] * g_hc[(size_t)jl[k] * OUT_F + f];
        if (part == 1) part2[f] = acc;
        __syncthreads();
        if (part == 0)
            out[(size_t)row * OUT_F + f] = (acc + part2[f]) * inv;
        return;
    }

    // slow path (degree > CAP): recompute Z, then chunked compaction+gather
    {
        float zloc = 0.f;
        w = word;
        while (w) {
            int bpos = __ffs(w) - 1; w &= w - 1;
            int j = (tid << 5) + bpos;
            float2 sd = g_sd[j];
            float a = ca * lrelu(sci + sd.x) + cs * lrelu(ssi + sd.y);
            zloc += __expf(a - m);
        }
        float Z = blockReduceSum(zloc, red);
        float inv = 1.f / Z;
        float acc = 0.f;
        for (int c = 0; c < NWORDS / 32; c++) {
            __syncthreads();
            if (tid == 0) s_cnt = 0;
            __syncthreads();
            if (tid < 32) {
                unsigned wd = g_adj[row * NWORDS + c * 32 + tid];
                int oo = atomicAdd(&s_cnt, __popc(wd));
                while (wd) {
                    int bpos = __ffs(wd) - 1; wd &= wd - 1;
                    int j = ((c * 32 + tid) << 5) + bpos;
                    float2 sd = g_sd[j];
                    float a = ca * lrelu(sci + sd.x) + cs * lrelu(ssi + sd.y);
                    wl[oo] = __expf(a - m);
                    jl[oo] = (unsigned short)j;
                    oo++;
                }
            }
            __syncthreads();
            int cc = s_cnt;
            for (int k = part; k < cc; k += 2)
                acc += wl[k] * g_hc[(size_t)jl[k] * OUT_F + f];
        }
        if (part == 1) part2[f] = acc;
        __syncthreads();
        if (part == 0)
            out[(size_t)row * OUT_F + f] = (acc + part2[f]) * inv;
    }
}

// ---------------- launch ----------------
extern "C" void kernel_launch(void* const* d_in, const int* in_sizes, int n_in,
                              void* d_out, int out_size) {
    const float* h_context   = (const float*)d_in[0];
    const float* h_structure = (const float*)d_in[1];
    const int*   edge        = (const int*)d_in[2];   // int32 or int64, detected on device
    const float* Wc_w        = (const float*)d_in[3];
    const float* Wc_b        = (const float*)d_in[4];
    const float* Ws_w        = (const float*)d_in[5];
    const float* Ws_b        = (const float*)d_in[6];
    const float* ac_w        = (const float*)d_in[7];
    const float* as_w        = (const float*)d_in[8];
    const float* Ws_coff     = (const float*)d_in[9];
    const float* Wc_coff     = (const float*)d_in[10];
    float* out = (float*)d_out;
    int E = in_sizes[2] / 2;

    k_init<<<(Nn * NWORDS / 4) / 256, 256>>>(edge, E);
    k_edges<<<(E + 255) / 256, 256>>>(edge, E, Ws_w, Ws_b, as_w, Ws_coff, Wc_coff);
    k_sscore<<<(Nn * 32) / 256, 256>>>(h_structure);
    k_gemm<<<Nn / BM, 256>>>(h_context, Wc_w, Wc_b, ac_w);
    k_attn<<<Nn, 256>>>(out, Ws_coff, Wc_coff);
}